// round 13
// baseline (speedup 1.0000x reference)
#include <cuda_runtime.h>
#include <cuda_fp16.h>

#define N 8192
#define C 10
#define Dd 6
#define BI 64
#define JCH 1024   // j-chunk per gemv block (jsplit = N/JCH = 8)

__device__ __half g_Ksp[(size_t)N * N];   // 134 MB
__device__ __half g_Kbl[(size_t)N * N];   // 134 MB
__device__ __half g_Ph[16 * N];           // P padded to 16 classes, fp16
__device__ float g_OSP[C * N];
__device__ float g_OBL[C * N];
__device__ float g_A[C * C];
__device__ float g_B[C * C];

// ---------------------------------------------------------------------------
// m16n8k16 HMMA, fp16 in / fp32 acc
// ---------------------------------------------------------------------------
__device__ __forceinline__ void mma16816(float& d0, float& d1, float& d2, float& d3,
                                         unsigned a0, unsigned a1, unsigned a2, unsigned a3,
                                         unsigned b0, unsigned b1) {
    asm volatile(
        "mma.sync.aligned.m16n8k16.row.col.f32.f16.f16.f32 "
        "{%0,%1,%2,%3}, {%4,%5,%6,%7}, {%8,%9}, {%0,%1,%2,%3};"
        : "+f"(d0), "+f"(d1), "+f"(d2), "+f"(d3)
        : "r"(a0), "r"(a1), "r"(a2), "r"(a3), "r"(b0), "r"(b1));
}

// ---------------------------------------------------------------------------
// Build both kernel matrices (fp16) once. Dot-product distance form.
// ---------------------------------------------------------------------------
__global__ __launch_bounds__(256) void build_K(const float* __restrict__ feat) {
    __shared__ float fis[Dd][BI];
    __shared__ float a3s[BI], a6s[BI];

    const int ib = blockIdx.y * BI;
    const int jp = blockIdx.x * 256 + threadIdx.x;
    const int j0 = jp * 2;

    if (threadIdx.x < BI) {
        float s3 = 0.f, s6 = 0.f;
#pragma unroll
        for (int d = 0; d < Dd; d++) {
            float v = feat[d * N + ib + threadIdx.x];
            fis[d][threadIdx.x] = v;
            if (d < 3) s3 += v * v; else s6 += v * v;
        }
        a3s[threadIdx.x] = s3;
        a6s[threadIdx.x] = s3 + s6;
    }
    __syncthreads();

    float fj[2][Dd], b3[2], b6[2];
#pragma unroll
    for (int t = 0; t < 2; t++) {
        float s3 = 0.f, s6 = 0.f;
#pragma unroll
        for (int d = 0; d < Dd; d++) {
            float v = feat[d * N + j0 + t];
            fj[t][d] = v;
            if (d < 3) s3 += v * v; else s6 += v * v;
        }
        b3[t] = s3;
        b6[t] = s3 + s6;
    }

#pragma unroll 4
    for (int r = 0; r < BI; r++) {
        float ksp[2], kbl[2];
#pragma unroll
        for (int t = 0; t < 2; t++) {
            float s3 = 0.f, s6 = 0.f;
#pragma unroll
            for (int d = 0; d < 3; d++) s3 = fmaf(fis[d][r], fj[t][d], s3);
            s6 = s3;
#pragma unroll
            for (int d = 3; d < Dd; d++) s6 = fmaf(fis[d][r], fj[t][d], s6);
            float d3 = a3s[r] + b3[t] - 2.f * s3;
            float d6 = a6s[r] + b6[t] - 2.f * s6;
            ksp[t] = __expf(d3 * (-1.f / 128.f));
            kbl[t] = __expf(-0.5f * d6);
        }
        size_t off = (size_t)(ib + r) * N + j0;
        *(__half2*)&g_Ksp[off] = __floats2half2_rn(ksp[0], ksp[1]);
        *(__half2*)&g_Kbl[off] = __floats2half2_rn(kbl[0], kbl[1]);
    }
}

// ---------------------------------------------------------------------------
__global__ void ab_k(const float* __restrict__ sw, const float* __restrict__ bw,
                     const float* __restrict__ cm) {
    int t = threadIdx.x;
    if (t < C * C) {
        int r = t / C, c = t % C;
        float a = 0.f, b = 0.f;
        for (int k = 0; k < C; k++) {
            a += cm[r * C + k] * sw[k * C + c];
            b += cm[r * C + k] * bw[k * C + c];
        }
        g_A[t] = a;
        g_B[t] = b;
    }
}

// Zero padding rows 10..15 of g_Ph (once; never written again).
__global__ void pad_k() {
    int idx = blockIdx.x * blockDim.x + threadIdx.x;
    if (idx < 6 * N) g_Ph[10 * N + idx] = __float2half(0.f);
}

// ---------------------------------------------------------------------------
// Initial softmax over classes (from unaries) -> g_Ph; zero accumulators.
// ---------------------------------------------------------------------------
__global__ __launch_bounds__(256) void softmax_k(const float* __restrict__ qin) {
    int i = blockIdx.x * blockDim.x + threadIdx.x;
    if (i >= N) return;
    float v[C];
    float m = -1e30f;
#pragma unroll
    for (int c = 0; c < C; c++) {
        v[c] = qin[c * N + i];
        m = fmaxf(m, v[c]);
    }
    float s = 0.f;
#pragma unroll
    for (int c = 0; c < C; c++) {
        v[c] = __expf(v[c] - m);
        s += v[c];
    }
    float inv = 1.0f / s;
#pragma unroll
    for (int c = 0; c < C; c++) {
        g_Ph[c * N + i] = __float2half(v[c] * inv);
        g_OSP[c * N + i] = 0.f;
        g_OBL[c * N + i] = 0.f;
    }
}

// ---------------------------------------------------------------------------
// Tensor-core GEMV: Out[16,N] += P16[16,jchunk] @ K[jchunk, i-range]
// Uses K symmetry: B(k=j, n=i) = K[i*N + j] -> contiguous half2 LDG per lane.
// Warp: 4 n-tiles of 8 i = 32 i, full j-chunk. Block: 4 warps = 128 i.
// grid = (N/128, N/JCH, 2). No smem. Commit via float2 atomics.
// ---------------------------------------------------------------------------
__global__ __launch_bounds__(128) void gemv_tc() {
    const __half* __restrict__ K = blockIdx.z ? g_Kbl : g_Ksp;
    float* __restrict__ outp = blockIdx.z ? g_OBL : g_OSP;

    const int tid = threadIdx.x;
    const int warp = tid >> 5, lane = tid & 31;
    const int gid = lane >> 2;          // 0..7
    const int tig = lane & 3;           // 0..3
    const int cb = blockIdx.y * JCH;
    const int ia = blockIdx.x * 128 + warp * 32;

    float acc[4][4];
#pragma unroll
    for (int t = 0; t < 4; t++)
#pragma unroll
        for (int r = 0; r < 4; r++) acc[t][r] = 0.f;

    // A pointers (P16, fp16): row gid / gid+8, col cb + tig*2
    const __half* pa0 = g_Ph + (size_t)gid * N + cb + tig * 2;
    const __half* pa1 = g_Ph + (size_t)(gid + 8) * N + cb + tig * 2;
    // B pointers: row (ia + t*8 + gid), col cb + tig*2
    const __half* pb = K + (size_t)(ia + gid) * N + cb + tig * 2;

#pragma unroll 2
    for (int js = 0; js < JCH; js += 16) {
        unsigned a0 = *(const unsigned*)(pa0 + js);
        unsigned a1 = *(const unsigned*)(pa1 + js);
        unsigned a2 = *(const unsigned*)(pa0 + js + 8);
        unsigned a3 = *(const unsigned*)(pa1 + js + 8);

        unsigned b[4][2];
#pragma unroll
        for (int t = 0; t < 4; t++) {
            const __half* p = pb + (size_t)t * 8 * N + js;
            b[t][0] = *(const unsigned*)p;
            b[t][1] = *(const unsigned*)(p + 8);
        }
#pragma unroll
        for (int t = 0; t < 4; t++)
            mma16816(acc[t][0], acc[t][1], acc[t][2], acc[t][3],
                     a0, a1, a2, a3, b[t][0], b[t][1]);
    }

    // Commit. D(row, col): row=gid (+8), col=tig*2,+1 within tile t.
#pragma unroll
    for (int t = 0; t < 4; t++) {
        int i0 = ia + t * 8 + tig * 2;
        atomicAdd((float2*)&outp[gid * N + i0], make_float2(acc[t][0], acc[t][1]));
        if (gid < 2)
            atomicAdd((float2*)&outp[(gid + 8) * N + i0], make_float2(acc[t][2], acc[t][3]));
    }
}

// ---------------------------------------------------------------------------
// Fused: q = unaries - (A @ sp + B @ bl); write q; if not last iteration,
// softmax(q) -> g_Ph (fp16) and zero accumulators for the next gemv.
// ---------------------------------------------------------------------------
__global__ __launch_bounds__(256) void update_k(const float* __restrict__ unaries,
                                                float* __restrict__ qout,
                                                int last) {
    __shared__ float As[C * C], Bs[C * C];
    if (threadIdx.x < C * C) {
        As[threadIdx.x] = g_A[threadIdx.x];
        Bs[threadIdx.x] = g_B[threadIdx.x];
    }
    __syncthreads();

    int i = blockIdx.x * blockDim.x + threadIdx.x;
    if (i >= N) return;

    float sp[C], bl[C];
#pragma unroll
    for (int k = 0; k < C; k++) {
        sp[k] = g_OSP[k * N + i];
        bl[k] = g_OBL[k * N + i];
    }

    float q[C];
#pragma unroll
    for (int c = 0; c < C; c++) {
        float pair = 0.f;
#pragma unroll
        for (int k = 0; k < C; k++)
            pair += As[c * C + k] * sp[k] + Bs[c * C + k] * bl[k];
        q[c] = unaries[c * N + i] - pair;
        qout[c * N + i] = q[c];
    }

    if (last) return;

    float m = -1e30f;
#pragma unroll
    for (int c = 0; c < C; c++) m = fmaxf(m, q[c]);
    float s = 0.f;
#pragma unroll
    for (int c = 0; c < C; c++) {
        q[c] = __expf(q[c] - m);
        s += q[c];
    }
    float inv = 1.0f / s;
#pragma unroll
    for (int c = 0; c < C; c++) {
        g_Ph[c * N + i] = __float2half(q[c] * inv);
        g_OSP[c * N + i] = 0.f;
        g_OBL[c * N + i] = 0.f;
    }
}

// ---------------------------------------------------------------------------
extern "C" void kernel_launch(void* const* d_in, const int* in_sizes, int n_in,
                              void* d_out, int out_size) {
    const float* unaries = (const float*)d_in[0];
    const float* feat = (const float*)d_in[1];
    const float* sw = (const float*)d_in[2];
    const float* bw = (const float*)d_in[3];
    const float* cm = (const float*)d_in[4];
    float* qout = (float*)d_out;

    build_K<<<dim3(N / 512, N / BI), 256>>>(feat);
    ab_k<<<1, 128>>>(sw, bw, cm);
    pad_k<<<(6 * N + 255) / 256, 256>>>();

    softmax_k<<<N / 256, 256>>>(unaries);
    for (int it = 0; it < 5; it++) {
        gemv_tc<<<dim3(N / 128, N / JCH, 2), 128>>>();
        update_k<<<N / 256, 256>>>(unaries, qout, it == 4);
    }
}

// round 14
// speedup vs baseline: 1.6086x; 1.6086x over previous
#include <cuda_runtime.h>
#include <cuda_fp16.h>

#define N 8192
#define C 10
#define Dd 6
#define BI 64
#define JSPLIT 8
#define CHUNK (N / JSPLIT)   // 1024 j per block
#define JB 64                // j per smem stage
#define BS_STRIDE 136        // halves per Bs row (128 + 8 pad -> 272B, conflict-free LDSM)
#define AS_STRIDE 72         // halves per As row (64 + 8 pad -> 144B)

__device__ __half g_Ksp[(size_t)N * N];   // 134 MB
__device__ __half g_Kbl[(size_t)N * N];   // 134 MB
__device__ __half g_Ph[16 * N];           // P padded to 16 classes, fp16
__device__ float g_OSP[C * N];
__device__ float g_OBL[C * N];
__device__ float g_A[C * C];
__device__ float g_B[C * C];

// ---------------------------------------------------------------------------
__device__ __forceinline__ void mma16816(float& d0, float& d1, float& d2, float& d3,
                                         unsigned a0, unsigned a1, unsigned a2, unsigned a3,
                                         unsigned b0, unsigned b1) {
    asm volatile(
        "mma.sync.aligned.m16n8k16.row.col.f32.f16.f16.f32 "
        "{%0,%1,%2,%3}, {%4,%5,%6,%7}, {%8,%9}, {%0,%1,%2,%3};"
        : "+f"(d0), "+f"(d1), "+f"(d2), "+f"(d3)
        : "r"(a0), "r"(a1), "r"(a2), "r"(a3), "r"(b0), "r"(b1));
}
__device__ __forceinline__ void ldsm_x4(unsigned& r0, unsigned& r1, unsigned& r2,
                                        unsigned& r3, unsigned addr) {
    asm volatile("ldmatrix.sync.aligned.m8n8.x4.shared.b16 {%0,%1,%2,%3}, [%4];"
                 : "=r"(r0), "=r"(r1), "=r"(r2), "=r"(r3) : "r"(addr));
}
__device__ __forceinline__ void ldsm_x4t(unsigned& r0, unsigned& r1, unsigned& r2,
                                         unsigned& r3, unsigned addr) {
    asm volatile("ldmatrix.sync.aligned.m8n8.x4.trans.shared.b16 {%0,%1,%2,%3}, [%4];"
                 : "=r"(r0), "=r"(r1), "=r"(r2), "=r"(r3) : "r"(addr));
}
__device__ __forceinline__ unsigned s2u(const void* p) {
    return (unsigned)__cvta_generic_to_shared(p);
}

// ---------------------------------------------------------------------------
// Build both kernel matrices (fp16) once. Dot-product distance form.
// ---------------------------------------------------------------------------
__global__ __launch_bounds__(256) void build_K(const float* __restrict__ feat) {
    __shared__ float fis[Dd][BI];
    __shared__ float a3s[BI], a6s[BI];

    const int ib = blockIdx.y * BI;
    const int jp = blockIdx.x * 256 + threadIdx.x;
    const int j0 = jp * 2;

    if (threadIdx.x < BI) {
        float s3 = 0.f, s6 = 0.f;
#pragma unroll
        for (int d = 0; d < Dd; d++) {
            float v = feat[d * N + ib + threadIdx.x];
            fis[d][threadIdx.x] = v;
            if (d < 3) s3 += v * v; else s6 += v * v;
        }
        a3s[threadIdx.x] = s3;
        a6s[threadIdx.x] = s3 + s6;
    }
    __syncthreads();

    float fj[2][Dd], b3[2], b6[2];
#pragma unroll
    for (int t = 0; t < 2; t++) {
        float s3 = 0.f, s6 = 0.f;
#pragma unroll
        for (int d = 0; d < Dd; d++) {
            float v = feat[d * N + j0 + t];
            fj[t][d] = v;
            if (d < 3) s3 += v * v; else s6 += v * v;
        }
        b3[t] = s3;
        b6[t] = s3 + s6;
    }

#pragma unroll 4
    for (int r = 0; r < BI; r++) {
        float ksp[2], kbl[2];
#pragma unroll
        for (int t = 0; t < 2; t++) {
            float s3 = 0.f, s6 = 0.f;
#pragma unroll
            for (int d = 0; d < 3; d++) s3 = fmaf(fis[d][r], fj[t][d], s3);
            s6 = s3;
#pragma unroll
            for (int d = 3; d < Dd; d++) s6 = fmaf(fis[d][r], fj[t][d], s6);
            float d3 = a3s[r] + b3[t] - 2.f * s3;
            float d6 = a6s[r] + b6[t] - 2.f * s6;
            ksp[t] = __expf(d3 * (-1.f / 128.f));
            kbl[t] = __expf(-0.5f * d6);
        }
        size_t off = (size_t)(ib + r) * N + j0;
        *(__half2*)&g_Ksp[off] = __floats2half2_rn(ksp[0], ksp[1]);
        *(__half2*)&g_Kbl[off] = __floats2half2_rn(kbl[0], kbl[1]);
    }
}

// ---------------------------------------------------------------------------
__global__ void ab_k(const float* __restrict__ sw, const float* __restrict__ bw,
                     const float* __restrict__ cm) {
    int t = threadIdx.x;
    if (t < C * C) {
        int r = t / C, c = t % C;
        float a = 0.f, b = 0.f;
        for (int k = 0; k < C; k++) {
            a += cm[r * C + k] * sw[k * C + c];
            b += cm[r * C + k] * bw[k * C + c];
        }
        g_A[t] = a;
        g_B[t] = b;
    }
}

// Zero padding rows 10..15 of g_Ph (once; never written again).
__global__ void pad_k() {
    int idx = blockIdx.x * blockDim.x + threadIdx.x;
    if (idx < 6 * N) g_Ph[10 * N + idx] = __float2half(0.f);
}

// ---------------------------------------------------------------------------
__global__ __launch_bounds__(256) void softmax_k(const float* __restrict__ qin) {
    int i = blockIdx.x * blockDim.x + threadIdx.x;
    if (i >= N) return;
    float v[C];
    float m = -1e30f;
#pragma unroll
    for (int c = 0; c < C; c++) {
        v[c] = qin[c * N + i];
        m = fmaxf(m, v[c]);
    }
    float s = 0.f;
#pragma unroll
    for (int c = 0; c < C; c++) {
        v[c] = __expf(v[c] - m);
        s += v[c];
    }
    float inv = 1.0f / s;
#pragma unroll
    for (int c = 0; c < C; c++) {
        g_Ph[c * N + i] = __float2half(v[c] * inv);
        g_OSP[c * N + i] = 0.f;
        g_OBL[c * N + i] = 0.f;
    }
}

// ---------------------------------------------------------------------------
// Smem-staged tensor-core GEMM: Out[16, i-tile] += P16[16, jchunk] @ K[jchunk, i]
// (B[k=j][n=i] = K[j*N+i] via symmetry; rows of K are contiguous in i.)
// Block 128 thr (4 warps), tile 16c x 128i, stage JB=64 j in smem.
// Fragments via ldmatrix (A) / ldmatrix.trans (B), padded conflict-free strides.
// grid = (N/128, JSPLIT, 2). Commit via float2 atomics.
// ---------------------------------------------------------------------------
__global__ __launch_bounds__(128) void gemv_tc() {
    __shared__ __half Bs[JB * BS_STRIDE];    // 17408 B
    __shared__ __half As[16 * AS_STRIDE];    // 2304 B

    const __half* __restrict__ K = blockIdx.z ? g_Kbl : g_Ksp;
    float* __restrict__ outp = blockIdx.z ? g_OBL : g_OSP;

    const int tid = threadIdx.x;
    const int warp = tid >> 5, lane = tid & 31;
    const int gid = lane >> 2, tig = lane & 3;
    const int cb = blockIdx.y * CHUNK;
    const int ia = blockIdx.x * 128;
    const int iw = warp * 32;

    float acc[4][4];
#pragma unroll
    for (int t = 0; t < 4; t++)
#pragma unroll
        for (int r = 0; r < 4; r++) acc[t][r] = 0.f;

    // ldmatrix lane-address bases (byte smem addresses)
    // A (x4): lanes 0-15 -> row (lane&15), k-col 0; lanes 16-31 -> row (lane-16), k-col 8
    const unsigned aBase = s2u(&As[(lane & 15) * AS_STRIDE + (lane >> 4) * 8]);
    // B (x4.trans): lanes 0-15 -> k-row (lane&15), n-col iw; lanes 16-31 -> n-col iw+8
    const unsigned bBase = s2u(&Bs[(lane & 15) * BS_STRIDE + iw + (lane >> 4) * 8]);

    for (int jj = 0; jj < CHUNK; jj += JB) {
        // fill Bs: K rows (cb+jj .. +JB), 128 i each — coalesced LDG.128
#pragma unroll
        for (int p = 0; p < 8; p++) {
            int idx = tid + p * 128;
            int row = idx >> 4, col = idx & 15;
            uint4 v = *(const uint4*)&K[(size_t)(cb + jj + row) * N + ia + col * 8];
            *(uint4*)&Bs[row * BS_STRIDE + col * 8] = v;
        }
        // fill As: P16 rows 0..15, JB j each
        {
            int row = tid >> 3, col = tid & 7;
            uint4 v = *(const uint4*)&g_Ph[(size_t)row * N + cb + jj + col * 8];
            *(uint4*)&As[row * AS_STRIDE + col * 8] = v;
        }
        __syncthreads();

#pragma unroll
        for (int ks = 0; ks < JB; ks += 16) {
            unsigned a0, a1, a2, a3;
            ldsm_x4(a0, a1, a2, a3, aBase + ks * 2);

            unsigned b0[4], b1[4];
            ldsm_x4t(b0[0], b0[1], b0[2], b0[3], bBase + ks * (BS_STRIDE * 2));
            ldsm_x4t(b1[0], b1[1], b1[2], b1[3], bBase + ks * (BS_STRIDE * 2) + 32);

            mma16816(acc[0][0], acc[0][1], acc[0][2], acc[0][3], a0, a1, a2, a3, b0[0], b0[1]);
            mma16816(acc[1][0], acc[1][1], acc[1][2], acc[1][3], a0, a1, a2, a3, b0[2], b0[3]);
            mma16816(acc[2][0], acc[2][1], acc[2][2], acc[2][3], a0, a1, a2, a3, b1[0], b1[1]);
            mma16816(acc[3][0], acc[3][1], acc[3][2], acc[3][3], a0, a1, a2, a3, b1[2], b1[3]);
        }
        __syncthreads();
    }

    // Commit. D tile t: rows gid / gid+8 (classes), cols tig*2,+1 at i = ia+iw+t*8
#pragma unroll
    for (int t = 0; t < 4; t++) {
        int i0 = ia + iw + t * 8 + tig * 2;
        atomicAdd((float2*)&outp[gid * N + i0], make_float2(acc[t][0], acc[t][1]));
        if (gid < 2)
            atomicAdd((float2*)&outp[(gid + 8) * N + i0], make_float2(acc[t][2], acc[t][3]));
    }
}

// ---------------------------------------------------------------------------
// Fused: q = unaries - (A @ sp + B @ bl); write q; if not last iteration,
// softmax(q) -> g_Ph (fp16) and zero accumulators for the next gemv.
// ---------------------------------------------------------------------------
__global__ __launch_bounds__(256) void update_k(const float* __restrict__ unaries,
                                                float* __restrict__ qout,
                                                int last) {
    __shared__ float As2[C * C], Bs2[C * C];
    if (threadIdx.x < C * C) {
        As2[threadIdx.x] = g_A[threadIdx.x];
        Bs2[threadIdx.x] = g_B[threadIdx.x];
    }
    __syncthreads();

    int i = blockIdx.x * blockDim.x + threadIdx.x;
    if (i >= N) return;

    float sp[C], bl[C];
#pragma unroll
    for (int k = 0; k < C; k++) {
        sp[k] = g_OSP[k * N + i];
        bl[k] = g_OBL[k * N + i];
    }

    float q[C];
#pragma unroll
    for (int c = 0; c < C; c++) {
        float pair = 0.f;
#pragma unroll
        for (int k = 0; k < C; k++)
            pair += As2[c * C + k] * sp[k] + Bs2[c * C + k] * bl[k];
        q[c] = unaries[c * N + i] - pair;
        qout[c * N + i] = q[c];
    }

    if (last) return;

    float m = -1e30f;
#pragma unroll
    for (int c = 0; c < C; c++) m = fmaxf(m, q[c]);
    float s = 0.f;
#pragma unroll
    for (int c = 0; c < C; c++) {
        q[c] = __expf(q[c] - m);
        s += q[c];
    }
    float inv = 1.0f / s;
#pragma unroll
    for (int c = 0; c < C; c++) {
        g_Ph[c * N + i] = __float2half(q[c] * inv);
        g_OSP[c * N + i] = 0.f;
        g_OBL[c * N + i] = 0.f;
    }
}

// ---------------------------------------------------------------------------
extern "C" void kernel_launch(void* const* d_in, const int* in_sizes, int n_in,
                              void* d_out, int out_size) {
    const float* unaries = (const float*)d_in[0];
    const float* feat = (const float*)d_in[1];
    const float* sw = (const float*)d_in[2];
    const float* bw = (const float*)d_in[3];
    const float* cm = (const float*)d_in[4];
    float* qout = (float*)d_out;

    build_K<<<dim3(N / 512, N / BI), 256>>>(feat);
    ab_k<<<1, 128>>>(sw, bw, cm);
    pad_k<<<(6 * N + 255) / 256, 256>>>();

    softmax_k<<<N / 256, 256>>>(unaries);
    for (int it = 0; it < 5; it++) {
        gemv_tc<<<dim3(N / 128, JSPLIT, 2), 128>>>();
        update_k<<<N / 256, 256>>>(unaries, qout, it == 4);
    }
}